// round 7
// baseline (speedup 1.0000x reference)
#include <cuda_runtime.h>
#include <math.h>

#define BB 4
#define TT 32
#define NN 20000
#define NE 320000
#define DG 64
#define DW 300
#define DH 256
#define HD 128
#define H3 384
#define DESC 16
#define NC 2000
#define VD 30000

// ---------------- scratch (static device memory; no allocations) ----------------
__device__ float g_qemb[BB][DH];
__device__ float g_qg[BB][DG];
__device__ float4 g_tokdot[VD];              // per-token dot with q_g (4 batches)
__device__ float g_P[(size_t)VD * DG];       // emb_desc @ W0
__device__ float g_hb[NN][BB][DG];
__device__ float g_agg[NN][BB][DG];
__device__ float g_s[BB][NN];
__device__ float g_stats[BB][2];
__device__ float g_nodeagg[BB][DG];
__device__ float g_hidden[BB][1024];
// CSR-by-destination
__device__ int   g_deg[NN];
__device__ int   g_off[NN + 1];
__device__ int   g_cur[NN];
__device__ int2  g_e2[NE];

// ---------------- k0: zero out / nodeagg / deg ----------------
__global__ __launch_bounds__(256) void k0(float* __restrict__ out) {
    int i = blockIdx.x * 256 + threadIdx.x;
    if (i < NN) g_deg[i] = 0;
    if (i < BB * NC) out[i] = 0.f;
    if (i < BB * DG) ((float*)g_nodeagg)[i] = 0.f;
}

// ---------------- CSR build (side stream) ----------------
__global__ __launch_bounds__(256) void k_hist(const int* __restrict__ edst) {
    int e = blockIdx.x * 256 + threadIdx.x;
    if (e < NE) atomicAdd(&g_deg[edst[e]], 1);
}

// hierarchical warp-shfl scan: 2 block barriers total
__global__ __launch_bounds__(1024) void k_scan() {
    __shared__ int sdeg[NN];          // 80KB
    __shared__ int wsum[32];
    int t = threadIdx.x;
    for (int i = t; i < NN; i += 1024) sdeg[i] = g_deg[i];
    __syncthreads();
    const int CHK = 20;
    int base = t * CHK;
    int loc[CHK];
    int s = 0;
#pragma unroll
    for (int k = 0; k < CHK; k++) {
        int idx = base + k;
        int d = (idx < NN) ? sdeg[idx] : 0;
        loc[k] = s;
        s += d;
    }
    int lane = t & 31, wid = t >> 5;
    int incl = s;
#pragma unroll
    for (int off = 1; off < 32; off <<= 1) {
        int v = __shfl_up_sync(0xffffffffu, incl, off);
        if (lane >= off) incl += v;
    }
    if (lane == 31) wsum[wid] = incl;
    __syncthreads();
    if (wid == 0) {
        int v = wsum[lane];
        int iv = v;
#pragma unroll
        for (int off = 1; off < 32; off <<= 1) {
            int u = __shfl_up_sync(0xffffffffu, iv, off);
            if (lane >= off) iv += u;
        }
        wsum[lane] = iv - v;   // exclusive warp offset
    }
    __syncthreads();
    int texcl = wsum[wid] + incl - s;  // exclusive prefix of this thread's chunk
#pragma unroll
    for (int k = 0; k < CHK; k++) {
        int idx = base + k;
        if (idx < NN) { int o = texcl + loc[k]; g_off[idx] = o; g_cur[idx] = o; }
    }
    if (t == 1023) g_off[NN] = wsum[31] + incl;   // == texcl + s
}

__global__ __launch_bounds__(256) void k_fill(
    const int* __restrict__ esrc, const int* __restrict__ edst,
    const int* __restrict__ etype, const float* __restrict__ wcomp) {
    int e = blockIdx.x * 256 + threadIdx.x;
    if (e >= NE) return;
    int d = edst[e];
    int pos = atomicAdd(&g_cur[d], 1);
    g_e2[pos] = make_int2(esrc[e], __float_as_int(wcomp[etype[e]]));
}

// ---------------- P = emb_desc @ W0 (stream 3; no q_g dependency) ----------------
// one warp per token, 8 warps/block
__global__ __launch_bounds__(256) void k_P(
    const float* __restrict__ emb_desc, const float* __restrict__ bases)
{
    __shared__ float sW0[DG * DG];
    __shared__ float sE[8][DG];
    int tid = threadIdx.x;
    for (int i = tid; i < DG * DG; i += 256) sW0[i] = bases[i];
    __syncthreads();
    int w = tid >> 5, lane = tid & 31;
    int v = blockIdx.x * 8 + w;
    if (v >= VD) return;
    float2 e = ((const float2*)(emb_desc + (size_t)v * DG))[lane];
    sE[w][2 * lane] = e.x;
    sE[w][2 * lane + 1] = e.y;
    __syncwarp();
    float ax = 0.f, ay = 0.f;
#pragma unroll
    for (int d = 0; d < DG; d++) {
        float fv = sE[w][d];
        float2 wv = *(float2*)&sW0[d * DG + 2 * lane];
        ax += fv * wv.x;
        ay += fv * wv.y;
    }
    ((float2*)(g_P + (size_t)v * DG))[lane] = make_float2(ax, ay);
}

// ---------------- tokdot[v][b] = emb_desc[v] . q_g[b] (after qg) ----------------
__global__ __launch_bounds__(256) void k_tokdot(const float* __restrict__ emb_desc)
{
    __shared__ float sQg[BB][DG];
    int tid = threadIdx.x;
    for (int i = tid; i < BB * DG; i += 256) ((float*)sQg)[i] = ((const float*)g_qg)[i];
    __syncthreads();
    int w = tid >> 5, lane = tid & 31;
    int v = blockIdx.x * 8 + w;
    if (v >= VD) return;
    float2 e = ((const float2*)(emb_desc + (size_t)v * DG))[lane];
    float p0 = e.x * sQg[0][2 * lane] + e.y * sQg[0][2 * lane + 1];
    float p1 = e.x * sQg[1][2 * lane] + e.y * sQg[1][2 * lane + 1];
    float p2 = e.x * sQg[2][2 * lane] + e.y * sQg[2][2 * lane + 1];
    float p3 = e.x * sQg[3][2 * lane] + e.y * sQg[3][2 * lane + 1];
#pragma unroll
    for (int off = 16; off; off >>= 1) {
        p0 += __shfl_xor_sync(0xffffffffu, p0, off);
        p1 += __shfl_xor_sync(0xffffffffu, p1, off);
        p2 += __shfl_xor_sync(0xffffffffu, p2, off);
        p3 += __shfl_xor_sync(0xffffffffu, p3, off);
    }
    if (lane == 0) g_tokdot[v] = make_float4(p0, p1, p2, p3);
}

// ---------------- fused gx + GRU scan: 8 blocks (dir x batch) x 768 threads ----------------
__global__ __launch_bounds__(768, 1) void k_gxgru(
    const int* __restrict__ questions, const float* __restrict__ emb_word,
    const float* __restrict__ Wxf, const float* __restrict__ bxf,
    const float* __restrict__ Wxb, const float* __restrict__ bxb,
    const float* __restrict__ Whf, const float* __restrict__ bhf,
    const float* __restrict__ Whb, const float* __restrict__ bhb)
{
    extern __shared__ float dyn[];
    float* xs = dyn;                 // [TT][DW]
    float* gx = dyn + TT * DW;       // [TT][H3]
    __shared__ float hs[HD];
    __shared__ float gsh[H3];
    __shared__ int msk[TT];
    int blk = blockIdx.x;
    int dir = blk >> 2, b = blk & 3;
    const float* Wx = dir ? Wxb : Wxf;
    const float* bx = dir ? bxb : bxf;
    const float* Wh = dir ? Whb : Whf;
    const float* bh = dir ? bhb : bhf;
    int tid = threadIdx.x;
    if (tid < TT) msk[tid] = questions[b * TT + tid];
    if (tid < HD) hs[tid] = 0.f;
    __syncthreads();
    for (int i = tid; i < TT * DW; i += 768) {
        int t = i / DW, k = i - t * DW;
        xs[i] = emb_word[(size_t)msk[t] * DW + k];
    }
    __syncthreads();
    {
        int g = tid % H3, tp = tid / H3;
        for (int t = tp; t < TT; t += 2) {
            int ts = dir ? (TT - 1 - t) : t;
            float a0 = 0.f, a1 = 0.f, a2 = 0.f, a3 = 0.f;
            const float* x = xs + t * DW;
#pragma unroll 4
            for (int i = 0; i < DW; i += 4) {
                a0 += x[i] * Wx[i * H3 + g];
                a1 += x[i + 1] * Wx[(i + 1) * H3 + g];
                a2 += x[i + 2] * Wx[(i + 2) * H3 + g];
                a3 += x[i + 3] * Wx[(i + 3) * H3 + g];
            }
            gx[ts * H3 + g] = bx[g] + a0 + a1 + a2 + a3;
        }
    }
    int col = tid >> 1, half = tid & 1;
    float w[64];
#pragma unroll
    for (int k = 0; k < 64; k++) w[k] = Wh[(half * 64 + k) * H3 + col];
    float bias = bh[col];
    __syncthreads();
    for (int t = 0; t < TT; t++) {
        float a0 = 0.f, a1 = 0.f, a2 = 0.f, a3 = 0.f;
#pragma unroll
        for (int k = 0; k < 64; k += 4) {
            a0 += hs[half * 64 + k] * w[k];
            a1 += hs[half * 64 + k + 1] * w[k + 1];
            a2 += hs[half * 64 + k + 2] * w[k + 2];
            a3 += hs[half * 64 + k + 3] * w[k + 3];
        }
        float acc = (a0 + a1) + (a2 + a3);
        acc += __shfl_xor_sync(0xffffffffu, acc, 1);
        if (half == 0) gsh[col] = acc + bias;
        __syncthreads();
        if (tid < HD) {
            const float* gxt = gx + t * H3;
            float r = 1.f / (1.f + expf(-(gxt[tid] + gsh[tid])));
            float z = 1.f / (1.f + expf(-(gxt[HD + tid] + gsh[HD + tid])));
            float n = tanhf(gxt[2 * HD + tid] + r * gsh[2 * HD + tid]);
            float h = hs[tid];
            float hnew = (1.f - z) * n + z * h;
            int torig = dir ? (TT - 1 - t) : t;
            hs[tid] = (msk[torig] != 0) ? hnew : h;
        }
        __syncthreads();
    }
    if (tid < HD) g_qemb[b][dir * HD + tid] = hs[tid];
}

// ---------------- q_g = q_emb @ W_hg + b_hg (32 blocks) ----------------
__global__ __launch_bounds__(256) void k_qg(const float* __restrict__ Whg, const float* __restrict__ bhg) {
    int blk = blockIdx.x;
    int b = blk >> 3, og = blk & 7;
    int i = threadIdx.x;
    float x = g_qemb[b][i];
    const float4* W4 = (const float4*)Whg;
    float4 wA = W4[i * 16 + og * 2];
    float4 wB = W4[i * 16 + og * 2 + 1];
    float p[8] = { x * wA.x, x * wA.y, x * wA.z, x * wA.w,
                   x * wB.x, x * wB.y, x * wB.z, x * wB.w };
#pragma unroll
    for (int o = 0; o < 8; o++)
#pragma unroll
        for (int off = 16; off; off >>= 1)
            p[o] += __shfl_down_sync(0xffffffffu, p[o], off);
    __shared__ float red[8][8];
    int wid = i >> 5, lane = i & 31;
    if (lane == 0)
#pragma unroll
        for (int o = 0; o < 8; o++) red[o][wid] = p[o];
    __syncthreads();
    if (i < 8) {
        float s = bhg[og * 8 + i];
#pragma unroll
        for (int k = 0; k < 8; k++) s += red[i][k];
        g_qg[b][og * 8 + i] = s;
    }
}

// ---------------- per-node: softmax over tokdots + weighted sum of P rows ----------------
__global__ __launch_bounds__(256) void k_node(const int* __restrict__ node_descs) {
    int tid = threadIdx.x;
    int w = tid >> 5, lane = tid & 31;
    int n = blockIdx.x * 8 + w;
    if (n >= NN) return;
    int tok = 0;
    float4 dv = make_float4(-1e30f, -1e30f, -1e30f, -1e30f);
    if (lane < DESC) {
        tok = node_descs[n * DESC + lane];
        dv = g_tokdot[tok];
    }
    float4 m = dv;
#pragma unroll
    for (int off = 8; off; off >>= 1) {
        m.x = fmaxf(m.x, __shfl_xor_sync(0xffffffffu, m.x, off, 16));
        m.y = fmaxf(m.y, __shfl_xor_sync(0xffffffffu, m.y, off, 16));
        m.z = fmaxf(m.z, __shfl_xor_sync(0xffffffffu, m.z, off, 16));
        m.w = fmaxf(m.w, __shfl_xor_sync(0xffffffffu, m.w, off, 16));
    }
    float4 ev;
    ev.x = expf(dv.x - m.x); ev.y = expf(dv.y - m.y);
    ev.z = expf(dv.z - m.z); ev.w = expf(dv.w - m.w);
    float4 s = ev;
#pragma unroll
    for (int off = 8; off; off >>= 1) {
        s.x += __shfl_xor_sync(0xffffffffu, s.x, off, 16);
        s.y += __shfl_xor_sync(0xffffffffu, s.y, off, 16);
        s.z += __shfl_xor_sync(0xffffffffu, s.z, off, 16);
        s.w += __shfl_xor_sync(0xffffffffu, s.w, off, 16);
    }
    float4 wt;
    wt.x = ev.x / s.x; wt.y = ev.y / s.y; wt.z = ev.z / s.z; wt.w = ev.w / s.w;
    float2 acc0 = make_float2(0.f, 0.f), acc1 = acc0, acc2 = acc0, acc3 = acc0;
#pragma unroll
    for (int i = 0; i < DESC; i++) {
        int ti = __shfl_sync(0xffffffffu, tok, i);
        float w0 = __shfl_sync(0xffffffffu, wt.x, i);
        float w1 = __shfl_sync(0xffffffffu, wt.y, i);
        float w2 = __shfl_sync(0xffffffffu, wt.z, i);
        float w3 = __shfl_sync(0xffffffffu, wt.w, i);
        float2 pv = ((const float2*)(g_P + (size_t)ti * DG))[lane];
        acc0.x += w0 * pv.x; acc0.y += w0 * pv.y;
        acc1.x += w1 * pv.x; acc1.y += w1 * pv.y;
        acc2.x += w2 * pv.x; acc2.y += w2 * pv.y;
        acc3.x += w3 * pv.x; acc3.y += w3 * pv.y;
    }
    ((float2*)&g_hb[n][0][0])[lane] = acc0;
    ((float2*)&g_hb[n][1][0])[lane] = acc1;
    ((float2*)&g_hb[n][2][0])[lane] = acc2;
    ((float2*)&g_hb[n][3][0])[lane] = acc3;
}

// ---------------- CSR gather + bias/relu + attn2 logits: 2 warps per node, unroll 4 ----------------
__global__ __launch_bounds__(256) void k_gather(const float* __restrict__ rbias) {
    int w = threadIdx.x >> 5, lane = threadIdx.x & 31;
    int n = blockIdx.x * 4 + (w >> 1);
    int half = w & 1;
    if (n >= NN) return;
    int off = g_off[n], end = g_off[n + 1];
    float4 aA = make_float4(0.f, 0.f, 0.f, 0.f);
    float4 aB = aA, aC = aA, aD = aA;
    const float4* hb4 = (const float4*)g_hb;
    int hoff = half * 32 + lane;
    for (int base = off; base < end; base += 32) {
        int ii = base + lane;
        int2 ed = (ii < end) ? g_e2[ii] : make_int2(0, 0);
        int m = min(32, end - base);
        int j = 0;
        for (; j + 4 <= m; j += 4) {
            int s0 = __shfl_sync(0xffffffffu, ed.x, j);
            float c0 = __int_as_float(__shfl_sync(0xffffffffu, ed.y, j));
            int s1 = __shfl_sync(0xffffffffu, ed.x, j + 1);
            float c1 = __int_as_float(__shfl_sync(0xffffffffu, ed.y, j + 1));
            int s2 = __shfl_sync(0xffffffffu, ed.x, j + 2);
            float c2 = __int_as_float(__shfl_sync(0xffffffffu, ed.y, j + 2));
            int s3 = __shfl_sync(0xffffffffu, ed.x, j + 3);
            float c3 = __int_as_float(__shfl_sync(0xffffffffu, ed.y, j + 3));
            float4 v0 = hb4[s0 * 64 + hoff];
            float4 v1 = hb4[s1 * 64 + hoff];
            float4 v2 = hb4[s2 * 64 + hoff];
            float4 v3 = hb4[s3 * 64 + hoff];
            aA.x += c0 * v0.x; aA.y += c0 * v0.y; aA.z += c0 * v0.z; aA.w += c0 * v0.w;
            aB.x += c1 * v1.x; aB.y += c1 * v1.y; aB.z += c1 * v1.z; aB.w += c1 * v1.w;
            aC.x += c2 * v2.x; aC.y += c2 * v2.y; aC.z += c2 * v2.z; aC.w += c2 * v2.w;
            aD.x += c3 * v3.x; aD.y += c3 * v3.y; aD.z += c3 * v3.z; aD.w += c3 * v3.w;
        }
        for (; j < m; j++) {
            int s0 = __shfl_sync(0xffffffffu, ed.x, j);
            float c0 = __int_as_float(__shfl_sync(0xffffffffu, ed.y, j));
            float4 v0 = hb4[s0 * 64 + hoff];
            aA.x += c0 * v0.x; aA.y += c0 * v0.y; aA.z += c0 * v0.z; aA.w += c0 * v0.w;
        }
    }
    float4 a = make_float4((aA.x + aB.x) + (aC.x + aD.x),
                           (aA.y + aB.y) + (aC.y + aD.y),
                           (aA.z + aB.z) + (aC.z + aD.z),
                           (aA.w + aB.w) + (aC.w + aD.w));
    const float4* rb4 = (const float4*)rbias;
    float4 rb = rb4[lane & 15];
    a.x = fmaxf(a.x + rb.x, 0.f); a.y = fmaxf(a.y + rb.y, 0.f);
    a.z = fmaxf(a.z + rb.z, 0.f); a.w = fmaxf(a.w + rb.w, 0.f);
    ((float4*)g_agg)[n * 64 + hoff] = a;
    const float4* qg4 = (const float4*)g_qg;
    float4 q = qg4[half * 32 + lane];
    float p = a.x * q.x + a.y * q.y + a.z * q.z + a.w * q.w;
#pragma unroll
    for (int o = 8; o; o >>= 1) p += __shfl_down_sync(0xffffffffu, p, o, 16);
    if (lane == 0)  g_s[2 * half][n] = p;
    if (lane == 16) g_s[2 * half + 1][n] = p;
}

// ---------------- softmax stats over nodes (4 blocks) ----------------
__global__ __launch_bounds__(512) void k_stats() {
    int b = blockIdx.x, tid = threadIdx.x;
    __shared__ float red[512];
    float m = -1e30f;
    for (int n = tid; n < NN; n += 512) m = fmaxf(m, g_s[b][n]);
    red[tid] = m;
    __syncthreads();
    for (int s = 256; s; s >>= 1) {
        if (tid < s) red[tid] = fmaxf(red[tid], red[tid + s]);
        __syncthreads();
    }
    m = red[0];
    __syncthreads();
    float sum = 0.f;
    for (int n = tid; n < NN; n += 512) sum += expf(g_s[b][n] - m);
    red[tid] = sum;
    __syncthreads();
    for (int s = 256; s; s >>= 1) {
        if (tid < s) red[tid] += red[tid + s];
        __syncthreads();
    }
    if (tid == 0) { g_stats[b][0] = m; g_stats[b][1] = 1.f / red[0]; }
}

// ---------------- attention pooling over nodes ----------------
#define CH 256
__global__ __launch_bounds__(256) void k_pool() {
    const int nch = (NN + CH - 1) / CH;
    int b = blockIdx.x / nch, c = blockIdx.x % nch;
    int n0 = c * CH;
    __shared__ float p[CH];
    __shared__ float part[4][DG];
    int tid = threadIdx.x;
    float m = g_stats[b][0], inv = g_stats[b][1];
    int n = n0 + tid;
    p[tid] = (n < NN) ? expf(g_s[b][n] - m) * inv : 0.f;
    __syncthreads();
    int d = tid & 63, g = tid >> 6;
    float acc = 0.f;
    for (int nl = g; nl < CH; nl += 4) {
        int nn2 = n0 + nl;
        if (nn2 < NN) acc += p[nl] * g_agg[nn2][b][d];
    }
    part[g][d] = acc;
    __syncthreads();
    if (tid < DG)
        atomicAdd(&g_nodeagg[b][tid], part[0][tid] + part[1][tid] + part[2][tid] + part[3][tid]);
}

// ---------------- classifier ----------------
__global__ __launch_bounds__(256) void k_fc1(const float* __restrict__ W1, const float* __restrict__ b1) {
    __shared__ float feat[BB][DG + DH];
    int tid = threadIdx.x;
    for (int i = tid; i < BB * (DG + DH); i += 256) {
        int b = i / (DG + DH), k = i % (DG + DH);
        feat[b][k] = (k < DG) ? g_nodeagg[b][k] : g_qemb[b][k - DG];
    }
    __syncthreads();
    int j = blockIdx.x * 256 + tid;
    float acc[BB] = {};
    for (int i = 0; i < DG + DH; i++) {
        float w = W1[i * 1024 + j];
#pragma unroll
        for (int b = 0; b < BB; b++) acc[b] += feat[b][i] * w;
    }
    float bj = b1[j];
#pragma unroll
    for (int b = 0; b < BB; b++) g_hidden[b][j] = fmaxf(acc[b] + bj, 0.f);
}

__global__ __launch_bounds__(256) void k_fc2(const float* __restrict__ W2, const float* __restrict__ b2,
                                             float* __restrict__ out) {
    int jb = blockIdx.x & 7, chunk = blockIdx.x >> 3;
    __shared__ float h[BB][256];
    int tid = threadIdx.x;
    for (int idx = tid; idx < BB * 256; idx += 256) {
        int b = idx >> 8, ii = idx & 255;
        h[b][ii] = g_hidden[b][chunk * 256 + ii];
    }
    __syncthreads();
    int j = jb * 256 + tid;
    if (j >= NC) return;
    float acc[BB] = {};
    for (int i = 0; i < 256; i++) {
        float w = W2[(size_t)(chunk * 256 + i) * NC + j];
#pragma unroll
        for (int b = 0; b < BB; b++) acc[b] += h[b][i] * w;
    }
    float bj = (chunk == 0) ? b2[j] : 0.f;
#pragma unroll
    for (int b = 0; b < BB; b++) atomicAdd(&out[b * NC + j], acc[b] + bj);
}

// ---------------- launch ----------------
extern "C" void kernel_launch(void* const* d_in, const int* in_sizes, int n_in,
                              void* d_out, int out_size) {
    const int*   questions  = (const int*)d_in[0];
    const int*   node_descs = (const int*)d_in[1];
    const int*   edge_src   = (const int*)d_in[2];
    const int*   edge_dst   = (const int*)d_in[3];
    const int*   edge_type  = (const int*)d_in[4];
    const float* emb_word   = (const float*)d_in[5];
    const float* emb_desc   = (const float*)d_in[6];
    const float* Wx_f       = (const float*)d_in[7];
    const float* Wh_f       = (const float*)d_in[8];
    const float* bx_f       = (const float*)d_in[9];
    const float* bh_f       = (const float*)d_in[10];
    const float* Wx_b       = (const float*)d_in[11];
    const float* Wh_b       = (const float*)d_in[12];
    const float* bx_b       = (const float*)d_in[13];
    const float* bh_b       = (const float*)d_in[14];
    const float* W_hg       = (const float*)d_in[15];
    const float* b_hg       = (const float*)d_in[16];
    const float* bases      = (const float*)d_in[17];
    const float* w_comp     = (const float*)d_in[18];
    const float* rgcn_bias  = (const float*)d_in[19];
    const float* W1         = (const float*)d_in[20];
    const float* b1         = (const float*)d_in[21];
    const float* W2         = (const float*)d_in[22];
    const float* b2         = (const float*)d_in[23];
    float* out = (float*)d_out;

    static cudaStream_t s2 = 0, s3 = 0;
    static cudaEvent_t evFork = 0, evCSR = 0, evP = 0;
    static int inited = 0;
    if (!inited) {
        cudaFuncSetAttribute(k_gxgru, cudaFuncAttributeMaxDynamicSharedMemorySize,
                             (TT * DW + TT * H3) * 4);
        cudaStreamCreateWithFlags(&s2, cudaStreamNonBlocking);
        cudaStreamCreateWithFlags(&s3, cudaStreamNonBlocking);
        cudaEventCreateWithFlags(&evFork, cudaEventDisableTiming);
        cudaEventCreateWithFlags(&evCSR, cudaEventDisableTiming);
        cudaEventCreateWithFlags(&evP, cudaEventDisableTiming);
        inited = 1;
    }

    // main stream start (zeroes deg too) + fork side streams
    k0<<<(NN + 255) / 256, 256>>>(out);
    cudaEventRecord(evFork, 0);
    cudaStreamWaitEvent(s2, evFork, 0);
    cudaStreamWaitEvent(s3, evFork, 0);

    // s2: CSR build
    k_hist<<<(NE + 255) / 256, 256, 0, s2>>>(edge_dst);
    k_scan<<<1, 1024, 0, s2>>>();
    k_fill<<<(NE + 255) / 256, 256, 0, s2>>>(edge_src, edge_dst, edge_type, w_comp);
    cudaEventRecord(evCSR, s2);

    // s3: P projection (independent of q_g)
    k_P<<<(VD + 7) / 8, 256, 0, s3>>>(emb_desc, bases);
    cudaEventRecord(evP, s3);

    // main: question encoding
    k_gxgru<<<8, 768, (TT * DW + TT * H3) * 4>>>(questions, emb_word,
        Wx_f, bx_f, Wx_b, bx_b, Wh_f, bh_f, Wh_b, bh_b);
    k_qg<<<32, 256>>>(W_hg, b_hg);
    k_tokdot<<<(VD + 7) / 8, 256>>>(emb_desc);
    cudaStreamWaitEvent(0, evP, 0);
    k_node<<<(NN + 7) / 8, 256>>>(node_descs);

    // join CSR, then gather + rest
    cudaStreamWaitEvent(0, evCSR, 0);
    k_gather<<<(NN + 3) / 4, 256>>>(rgcn_bias);
    k_stats<<<4, 512>>>();
    k_pool<<<4 * ((NN + CH - 1) / CH), 256>>>();
    k_fc1<<<4, 256>>>(W1, b1);
    k_fc2<<<32, 256>>>(W2, b2, out);
}

// round 8
// speedup vs baseline: 1.0596x; 1.0596x over previous
#include <cuda_runtime.h>
#include <math.h>

#define BB 4
#define TT 32
#define NN 20000
#define NE 320000
#define DG 64
#define DW 300
#define DH 256
#define HD 128
#define H3 384
#define DESC 16
#define NC 2000
#define VD 30000

// ---------------- scratch (static device memory; no allocations) ----------------
__device__ float g_qemb[BB][DH];
__device__ float g_qg[BB][DG];
__device__ float4 g_tokdot[VD];              // per-token dot with q_g (4 batches)
__device__ float g_P[(size_t)VD * DG];       // emb_desc @ W0
__device__ float g_hb[NN][BB][DG];
__device__ float g_agg[NN][BB][DG];
__device__ float g_s[BB][NN];
__device__ float g_stats[BB][2];
__device__ float g_nodeagg[BB][DG];
__device__ float g_hidden[BB][1024];
// CSR-by-destination
__device__ int   g_deg[NN];
__device__ int   g_off[NN + 1];
__device__ int   g_cur[NN];
__device__ int2  g_e2[NE];

// ---------------- k0: zero out / nodeagg / deg ----------------
__global__ __launch_bounds__(256) void k0(float* __restrict__ out) {
    int i = blockIdx.x * 256 + threadIdx.x;
    if (i < NN) g_deg[i] = 0;
    if (i < BB * NC) out[i] = 0.f;
    if (i < BB * DG) ((float*)g_nodeagg)[i] = 0.f;
}

// ---------------- CSR build (side stream) ----------------
__global__ __launch_bounds__(256) void k_hist(const int* __restrict__ edst) {
    int e = blockIdx.x * 256 + threadIdx.x;
    if (e < NE) atomicAdd(&g_deg[edst[e]], 1);
}

// hierarchical warp-shfl scan: 2 block barriers total
__global__ __launch_bounds__(1024) void k_scan() {
    __shared__ int sdeg[NN];          // 80KB
    __shared__ int wsum[32];
    int t = threadIdx.x;
    for (int i = t; i < NN; i += 1024) sdeg[i] = g_deg[i];
    __syncthreads();
    const int CHK = 20;
    int base = t * CHK;
    int loc[CHK];
    int s = 0;
#pragma unroll
    for (int k = 0; k < CHK; k++) {
        int idx = base + k;
        int d = (idx < NN) ? sdeg[idx] : 0;
        loc[k] = s;
        s += d;
    }
    int lane = t & 31, wid = t >> 5;
    int incl = s;
#pragma unroll
    for (int off = 1; off < 32; off <<= 1) {
        int v = __shfl_up_sync(0xffffffffu, incl, off);
        if (lane >= off) incl += v;
    }
    if (lane == 31) wsum[wid] = incl;
    __syncthreads();
    if (wid == 0) {
        int v = wsum[lane];
        int iv = v;
#pragma unroll
        for (int off = 1; off < 32; off <<= 1) {
            int u = __shfl_up_sync(0xffffffffu, iv, off);
            if (lane >= off) iv += u;
        }
        wsum[lane] = iv - v;   // exclusive warp offset
    }
    __syncthreads();
    int texcl = wsum[wid] + incl - s;  // exclusive prefix of this thread's chunk
#pragma unroll
    for (int k = 0; k < CHK; k++) {
        int idx = base + k;
        if (idx < NN) { int o = texcl + loc[k]; g_off[idx] = o; g_cur[idx] = o; }
    }
    if (t == 1023) g_off[NN] = wsum[31] + incl;
}

__global__ __launch_bounds__(256) void k_fill(
    const int* __restrict__ esrc, const int* __restrict__ edst,
    const int* __restrict__ etype, const float* __restrict__ wcomp) {
    int e = blockIdx.x * 256 + threadIdx.x;
    if (e >= NE) return;
    int d = edst[e];
    int pos = atomicAdd(&g_cur[d], 1);
    g_e2[pos] = make_int2(esrc[e], __float_as_int(wcomp[etype[e]]));
}

// ---------------- fused gx + GRU scan: 8 blocks (dir x batch) x 768 threads ----------------
__global__ __launch_bounds__(768, 1) void k_gxgru(
    const int* __restrict__ questions, const float* __restrict__ emb_word,
    const float* __restrict__ Wxf, const float* __restrict__ bxf,
    const float* __restrict__ Wxb, const float* __restrict__ bxb,
    const float* __restrict__ Whf, const float* __restrict__ bhf,
    const float* __restrict__ Whb, const float* __restrict__ bhb)
{
    extern __shared__ float dyn[];
    float* xs = dyn;                 // [TT][DW]
    float* gx = dyn + TT * DW;       // [TT][H3]
    __shared__ float hs[HD];
    __shared__ float gsh[H3];
    __shared__ int msk[TT];
    int blk = blockIdx.x;
    int dir = blk >> 2, b = blk & 3;
    const float* Wx = dir ? Wxb : Wxf;
    const float* bx = dir ? bxb : bxf;
    const float* Wh = dir ? Whb : Whf;
    const float* bh = dir ? bhb : bhf;
    int tid = threadIdx.x;
    if (tid < TT) msk[tid] = questions[b * TT + tid];
    if (tid < HD) hs[tid] = 0.f;
    __syncthreads();
    for (int i = tid; i < TT * DW; i += 768) {
        int t = i / DW, k = i - t * DW;
        xs[i] = emb_word[(size_t)msk[t] * DW + k];
    }
    __syncthreads();
    {
        int g = tid % H3, tp = tid / H3;
        for (int t = tp; t < TT; t += 2) {
            int ts = dir ? (TT - 1 - t) : t;
            float a0 = 0.f, a1 = 0.f, a2 = 0.f, a3 = 0.f;
            const float* x = xs + t * DW;
#pragma unroll 4
            for (int i = 0; i < DW; i += 4) {
                a0 += x[i] * Wx[i * H3 + g];
                a1 += x[i + 1] * Wx[(i + 1) * H3 + g];
                a2 += x[i + 2] * Wx[(i + 2) * H3 + g];
                a3 += x[i + 3] * Wx[(i + 3) * H3 + g];
            }
            gx[ts * H3 + g] = bx[g] + a0 + a1 + a2 + a3;
        }
    }
    int col = tid >> 1, half = tid & 1;
    float w[64];
#pragma unroll
    for (int k = 0; k < 64; k++) w[k] = Wh[(half * 64 + k) * H3 + col];
    float bias = bh[col];
    __syncthreads();
    for (int t = 0; t < TT; t++) {
        float a0 = 0.f, a1 = 0.f, a2 = 0.f, a3 = 0.f;
#pragma unroll
        for (int k = 0; k < 64; k += 4) {
            a0 += hs[half * 64 + k] * w[k];
            a1 += hs[half * 64 + k + 1] * w[k + 1];
            a2 += hs[half * 64 + k + 2] * w[k + 2];
            a3 += hs[half * 64 + k + 3] * w[k + 3];
        }
        float acc = (a0 + a1) + (a2 + a3);
        acc += __shfl_xor_sync(0xffffffffu, acc, 1);
        if (half == 0) gsh[col] = acc + bias;
        __syncthreads();
        if (tid < HD) {
            const float* gxt = gx + t * H3;
            float r = 1.f / (1.f + expf(-(gxt[tid] + gsh[tid])));
            float z = 1.f / (1.f + expf(-(gxt[HD + tid] + gsh[HD + tid])));
            float n = tanhf(gxt[2 * HD + tid] + r * gsh[2 * HD + tid]);
            float h = hs[tid];
            float hnew = (1.f - z) * n + z * h;
            int torig = dir ? (TT - 1 - t) : t;
            hs[tid] = (msk[torig] != 0) ? hnew : h;
        }
        __syncthreads();
    }
    if (tid < HD) g_qemb[b][dir * HD + tid] = hs[tid];
}

// ---------------- q_g = q_emb @ W_hg + b_hg (32 blocks) ----------------
__global__ __launch_bounds__(256) void k_qg(const float* __restrict__ Whg, const float* __restrict__ bhg) {
    int blk = blockIdx.x;
    int b = blk >> 3, og = blk & 7;
    int i = threadIdx.x;
    float x = g_qemb[b][i];
    const float4* W4 = (const float4*)Whg;
    float4 wA = W4[i * 16 + og * 2];
    float4 wB = W4[i * 16 + og * 2 + 1];
    float p[8] = { x * wA.x, x * wA.y, x * wA.z, x * wA.w,
                   x * wB.x, x * wB.y, x * wB.z, x * wB.w };
#pragma unroll
    for (int o = 0; o < 8; o++)
#pragma unroll
        for (int off = 16; off; off >>= 1)
            p[o] += __shfl_down_sync(0xffffffffu, p[o], off);
    __shared__ float red[8][8];
    int wid = i >> 5, lane = i & 31;
    if (lane == 0)
#pragma unroll
        for (int o = 0; o < 8; o++) red[o][wid] = p[o];
    __syncthreads();
    if (i < 8) {
        float s = bhg[og * 8 + i];
#pragma unroll
        for (int k = 0; k < 8; k++) s += red[i][k];
        g_qg[b][og * 8 + i] = s;
    }
}

// ---------------- per-token precompute: tokdot[v][b] and P = emb_desc @ W0 ----------------
// one warp per token, 8 warps/block (single pass over emb_desc)
__global__ __launch_bounds__(256) void k_tok(
    const float* __restrict__ emb_desc, const float* __restrict__ bases)
{
    __shared__ float sW0[DG * DG];
    __shared__ float sQg[BB][DG];
    __shared__ float sE[8][DG];
    int tid = threadIdx.x;
    for (int i = tid; i < DG * DG; i += 256) sW0[i] = bases[i];
    for (int i = tid; i < BB * DG; i += 256) ((float*)sQg)[i] = ((const float*)g_qg)[i];
    __syncthreads();
    int w = tid >> 5, lane = tid & 31;
    int v = blockIdx.x * 8 + w;
    if (v >= VD) return;
    float2 e = ((const float2*)(emb_desc + (size_t)v * DG))[lane];
    sE[w][2 * lane] = e.x;
    sE[w][2 * lane + 1] = e.y;
    __syncwarp();
    float p0 = e.x * sQg[0][2 * lane] + e.y * sQg[0][2 * lane + 1];
    float p1 = e.x * sQg[1][2 * lane] + e.y * sQg[1][2 * lane + 1];
    float p2 = e.x * sQg[2][2 * lane] + e.y * sQg[2][2 * lane + 1];
    float p3 = e.x * sQg[3][2 * lane] + e.y * sQg[3][2 * lane + 1];
#pragma unroll
    for (int off = 16; off; off >>= 1) {
        p0 += __shfl_xor_sync(0xffffffffu, p0, off);
        p1 += __shfl_xor_sync(0xffffffffu, p1, off);
        p2 += __shfl_xor_sync(0xffffffffu, p2, off);
        p3 += __shfl_xor_sync(0xffffffffu, p3, off);
    }
    if (lane == 0) g_tokdot[v] = make_float4(p0, p1, p2, p3);
    float ax = 0.f, ay = 0.f;
#pragma unroll
    for (int d = 0; d < DG; d++) {
        float fv = sE[w][d];
        float2 wv = *(float2*)&sW0[d * DG + 2 * lane];
        ax += fv * wv.x;
        ay += fv * wv.y;
    }
    ((float2*)(g_P + (size_t)v * DG))[lane] = make_float2(ax, ay);
}

// ---------------- per-node: softmax over gathered tokdots + weighted sum of P rows ----------------
__global__ __launch_bounds__(256) void k_node(const int* __restrict__ node_descs) {
    int tid = threadIdx.x;
    int w = tid >> 5, lane = tid & 31;
    int n = blockIdx.x * 8 + w;
    if (n >= NN) return;
    int tok = 0;
    float4 dv = make_float4(-1e30f, -1e30f, -1e30f, -1e30f);
    if (lane < DESC) {
        tok = node_descs[n * DESC + lane];
        dv = g_tokdot[tok];
    }
    float4 m = dv;
#pragma unroll
    for (int off = 8; off; off >>= 1) {
        m.x = fmaxf(m.x, __shfl_xor_sync(0xffffffffu, m.x, off, 16));
        m.y = fmaxf(m.y, __shfl_xor_sync(0xffffffffu, m.y, off, 16));
        m.z = fmaxf(m.z, __shfl_xor_sync(0xffffffffu, m.z, off, 16));
        m.w = fmaxf(m.w, __shfl_xor_sync(0xffffffffu, m.w, off, 16));
    }
    float4 ev;
    ev.x = expf(dv.x - m.x); ev.y = expf(dv.y - m.y);
    ev.z = expf(dv.z - m.z); ev.w = expf(dv.w - m.w);
    float4 s = ev;
#pragma unroll
    for (int off = 8; off; off >>= 1) {
        s.x += __shfl_xor_sync(0xffffffffu, s.x, off, 16);
        s.y += __shfl_xor_sync(0xffffffffu, s.y, off, 16);
        s.z += __shfl_xor_sync(0xffffffffu, s.z, off, 16);
        s.w += __shfl_xor_sync(0xffffffffu, s.w, off, 16);
    }
    float4 wt;
    wt.x = ev.x / s.x; wt.y = ev.y / s.y; wt.z = ev.z / s.z; wt.w = ev.w / s.w;
    float2 acc0 = make_float2(0.f, 0.f), acc1 = acc0, acc2 = acc0, acc3 = acc0;
#pragma unroll
    for (int i = 0; i < DESC; i++) {
        int ti = __shfl_sync(0xffffffffu, tok, i);
        float w0 = __shfl_sync(0xffffffffu, wt.x, i);
        float w1 = __shfl_sync(0xffffffffu, wt.y, i);
        float w2 = __shfl_sync(0xffffffffu, wt.z, i);
        float w3 = __shfl_sync(0xffffffffu, wt.w, i);
        float2 pv = ((const float2*)(g_P + (size_t)ti * DG))[lane];
        acc0.x += w0 * pv.x; acc0.y += w0 * pv.y;
        acc1.x += w1 * pv.x; acc1.y += w1 * pv.y;
        acc2.x += w2 * pv.x; acc2.y += w2 * pv.y;
        acc3.x += w3 * pv.x; acc3.y += w3 * pv.y;
    }
    ((float2*)&g_hb[n][0][0])[lane] = acc0;
    ((float2*)&g_hb[n][1][0])[lane] = acc1;
    ((float2*)&g_hb[n][2][0])[lane] = acc2;
    ((float2*)&g_hb[n][3][0])[lane] = acc3;
}

// ---------------- CSR gather + bias/relu + attn2 logits: 2 warps per node ----------------
__global__ __launch_bounds__(256) void k_gather(const float* __restrict__ rbias) {
    int w = threadIdx.x >> 5, lane = threadIdx.x & 31;
    int n = blockIdx.x * 4 + (w >> 1);
    int half = w & 1;
    if (n >= NN) return;
    int off = g_off[n], end = g_off[n + 1];
    float4 aA = make_float4(0.f, 0.f, 0.f, 0.f);
    float4 aB = make_float4(0.f, 0.f, 0.f, 0.f);
    const float4* hb4 = (const float4*)g_hb;
    int hoff = half * 32 + lane;
    for (int base = off; base < end; base += 32) {
        int ii = base + lane;
        int2 ed = (ii < end) ? g_e2[ii] : make_int2(0, 0);
        int m = min(32, end - base);
        int j = 0;
        for (; j + 2 <= m; j += 2) {
            int s0 = __shfl_sync(0xffffffffu, ed.x, j);
            float c0 = __int_as_float(__shfl_sync(0xffffffffu, ed.y, j));
            int s1 = __shfl_sync(0xffffffffu, ed.x, j + 1);
            float c1 = __int_as_float(__shfl_sync(0xffffffffu, ed.y, j + 1));
            float4 v0 = hb4[s0 * 64 + hoff];
            float4 v1 = hb4[s1 * 64 + hoff];
            aA.x += c0 * v0.x; aA.y += c0 * v0.y; aA.z += c0 * v0.z; aA.w += c0 * v0.w;
            aB.x += c1 * v1.x; aB.y += c1 * v1.y; aB.z += c1 * v1.z; aB.w += c1 * v1.w;
        }
        if (j < m) {
            int s0 = __shfl_sync(0xffffffffu, ed.x, j);
            float c0 = __int_as_float(__shfl_sync(0xffffffffu, ed.y, j));
            float4 v0 = hb4[s0 * 64 + hoff];
            aA.x += c0 * v0.x; aA.y += c0 * v0.y; aA.z += c0 * v0.z; aA.w += c0 * v0.w;
        }
    }
    float4 a = make_float4(aA.x + aB.x, aA.y + aB.y, aA.z + aB.z, aA.w + aB.w);
    const float4* rb4 = (const float4*)rbias;
    float4 rb = rb4[lane & 15];
    a.x = fmaxf(a.x + rb.x, 0.f); a.y = fmaxf(a.y + rb.y, 0.f);
    a.z = fmaxf(a.z + rb.z, 0.f); a.w = fmaxf(a.w + rb.w, 0.f);
    ((float4*)g_agg)[n * 64 + hoff] = a;
    const float4* qg4 = (const float4*)g_qg;
    float4 q = qg4[half * 32 + lane];
    float p = a.x * q.x + a.y * q.y + a.z * q.z + a.w * q.w;
#pragma unroll
    for (int o = 8; o; o >>= 1) p += __shfl_down_sync(0xffffffffu, p, o, 16);
    if (lane == 0)  g_s[2 * half][n] = p;
    if (lane == 16) g_s[2 * half + 1][n] = p;
}

// ---------------- softmax stats over nodes (4 blocks) ----------------
__global__ __launch_bounds__(512) void k_stats() {
    int b = blockIdx.x, tid = threadIdx.x;
    __shared__ float red[512];
    float m = -1e30f;
    for (int n = tid; n < NN; n += 512) m = fmaxf(m, g_s[b][n]);
    red[tid] = m;
    __syncthreads();
    for (int s = 256; s; s >>= 1) {
        if (tid < s) red[tid] = fmaxf(red[tid], red[tid + s]);
        __syncthreads();
    }
    m = red[0];
    __syncthreads();
    float sum = 0.f;
    for (int n = tid; n < NN; n += 512) sum += expf(g_s[b][n] - m);
    red[tid] = sum;
    __syncthreads();
    for (int s = 256; s; s >>= 1) {
        if (tid < s) red[tid] += red[tid + s];
        __syncthreads();
    }
    if (tid == 0) { g_stats[b][0] = m; g_stats[b][1] = 1.f / red[0]; }
}

// ---------------- attention pooling over nodes ----------------
#define CH 256
__global__ __launch_bounds__(256) void k_pool() {
    const int nch = (NN + CH - 1) / CH;
    int b = blockIdx.x / nch, c = blockIdx.x % nch;
    int n0 = c * CH;
    __shared__ float p[CH];
    __shared__ float part[4][DG];
    int tid = threadIdx.x;
    float m = g_stats[b][0], inv = g_stats[b][1];
    int n = n0 + tid;
    p[tid] = (n < NN) ? expf(g_s[b][n] - m) * inv : 0.f;
    __syncthreads();
    int d = tid & 63, g = tid >> 6;
    float acc = 0.f;
    for (int nl = g; nl < CH; nl += 4) {
        int nn2 = n0 + nl;
        if (nn2 < NN) acc += p[nl] * g_agg[nn2][b][d];
    }
    part[g][d] = acc;
    __syncthreads();
    if (tid < DG)
        atomicAdd(&g_nodeagg[b][tid], part[0][tid] + part[1][tid] + part[2][tid] + part[3][tid]);
}

// ---------------- classifier ----------------
__global__ __launch_bounds__(256) void k_fc1(const float* __restrict__ W1, const float* __restrict__ b1) {
    __shared__ float feat[BB][DG + DH];
    int tid = threadIdx.x;
    for (int i = tid; i < BB * (DG + DH); i += 256) {
        int b = i / (DG + DH), k = i % (DG + DH);
        feat[b][k] = (k < DG) ? g_nodeagg[b][k] : g_qemb[b][k - DG];
    }
    __syncthreads();
    int j = blockIdx.x * 256 + tid;
    float acc[BB] = {};
    for (int i = 0; i < DG + DH; i++) {
        float w = W1[i * 1024 + j];
#pragma unroll
        for (int b = 0; b < BB; b++) acc[b] += feat[b][i] * w;
    }
    float bj = b1[j];
#pragma unroll
    for (int b = 0; b < BB; b++) g_hidden[b][j] = fmaxf(acc[b] + bj, 0.f);
}

__global__ __launch_bounds__(256) void k_fc2(const float* __restrict__ W2, const float* __restrict__ b2,
                                             float* __restrict__ out) {
    int jb = blockIdx.x & 7, chunk = blockIdx.x >> 3;
    __shared__ float h[BB][256];
    int tid = threadIdx.x;
    for (int idx = tid; idx < BB * 256; idx += 256) {
        int b = idx >> 8, ii = idx & 255;
        h[b][ii] = g_hidden[b][chunk * 256 + ii];
    }
    __syncthreads();
    int j = jb * 256 + tid;
    if (j >= NC) return;
    float acc[BB] = {};
    for (int i = 0; i < 256; i++) {
        float w = W2[(size_t)(chunk * 256 + i) * NC + j];
#pragma unroll
        for (int b = 0; b < BB; b++) acc[b] += h[b][i] * w;
    }
    float bj = (chunk == 0) ? b2[j] : 0.f;
#pragma unroll
    for (int b = 0; b < BB; b++) atomicAdd(&out[b * NC + j], acc[b] + bj);
}

// ---------------- launch ----------------
extern "C" void kernel_launch(void* const* d_in, const int* in_sizes, int n_in,
                              void* d_out, int out_size) {
    const int*   questions  = (const int*)d_in[0];
    const int*   node_descs = (const int*)d_in[1];
    const int*   edge_src   = (const int*)d_in[2];
    const int*   edge_dst   = (const int*)d_in[3];
    const int*   edge_type  = (const int*)d_in[4];
    const float* emb_word   = (const float*)d_in[5];
    const float* emb_desc   = (const float*)d_in[6];
    const float* Wx_f       = (const float*)d_in[7];
    const float* Wh_f       = (const float*)d_in[8];
    const float* bx_f       = (const float*)d_in[9];
    const float* bh_f       = (const float*)d_in[10];
    const float* Wx_b       = (const float*)d_in[11];
    const float* Wh_b       = (const float*)d_in[12];
    const float* bx_b       = (const float*)d_in[13];
    const float* bh_b       = (const float*)d_in[14];
    const float* W_hg       = (const float*)d_in[15];
    const float* b_hg       = (const float*)d_in[16];
    const float* bases      = (const float*)d_in[17];
    const float* w_comp     = (const float*)d_in[18];
    const float* rgcn_bias  = (const float*)d_in[19];
    const float* W1         = (const float*)d_in[20];
    const float* b1         = (const float*)d_in[21];
    const float* W2         = (const float*)d_in[22];
    const float* b2         = (const float*)d_in[23];
    float* out = (float*)d_out;

    static cudaStream_t s2 = 0;
    static cudaEvent_t evFork = 0, evCSR = 0;
    static int inited = 0;
    if (!inited) {
        cudaFuncSetAttribute(k_gxgru, cudaFuncAttributeMaxDynamicSharedMemorySize,
                             (TT * DW + TT * H3) * 4);
        cudaStreamCreateWithFlags(&s2, cudaStreamNonBlocking);
        cudaEventCreateWithFlags(&evFork, cudaEventDisableTiming);
        cudaEventCreateWithFlags(&evCSR, cudaEventDisableTiming);
        inited = 1;
    }

    // main stream start (zeroes deg too) + fork side stream for CSR build
    k0<<<(NN + 255) / 256, 256>>>(out);
    cudaEventRecord(evFork, 0);
    cudaStreamWaitEvent(s2, evFork, 0);
    k_hist<<<(NE + 255) / 256, 256, 0, s2>>>(edge_dst);
    k_scan<<<1, 1024, 0, s2>>>();
    k_fill<<<(NE + 255) / 256, 256, 0, s2>>>(edge_src, edge_dst, edge_type, w_comp);
    cudaEventRecord(evCSR, s2);

    // main stream: question encoding + node features
    k_gxgru<<<8, 768, (TT * DW + TT * H3) * 4>>>(questions, emb_word,
        Wx_f, bx_f, Wx_b, bx_b, Wh_f, bh_f, Wh_b, bh_b);
    k_qg<<<32, 256>>>(W_hg, b_hg);
    k_tok<<<(VD + 7) / 8, 256>>>(emb_desc, bases);
    k_node<<<(NN + 7) / 8, 256>>>(node_descs);

    // join CSR, then gather + rest
    cudaStreamWaitEvent(0, evCSR, 0);
    k_gather<<<(NN + 3) / 4, 256>>>(rgcn_bias);
    k_stats<<<4, 512>>>();
    k_pool<<<4 * ((NN + CH - 1) / CH), 256>>>();
    k_fc1<<<4, 256>>>(W1, b1);
    k_fc2<<<32, 256>>>(W2, b2, out);
}

// round 9
// speedup vs baseline: 1.4001x; 1.3213x over previous
#include <cuda_runtime.h>
#include <math.h>

#define BB 4
#define TT 32
#define NN 20000
#define NE 320000
#define DG 64
#define DW 300
#define DH 256
#define HD 128
#define H3 384
#define DESC 16
#define NC 2000
#define VD 30000

// ---------------- scratch (static device memory; no allocations) ----------------
__device__ float g_gx[2][BB][TT][H3];        // input gates, scan-step indexed
__device__ float g_qemb[BB][DH];
__device__ float g_qg[BB][DG];
__device__ float4 g_tokdot[VD];
__device__ float g_P[(size_t)VD * DG];
__device__ float g_hb[NN][BB][DG];
__device__ float g_agg[NN][BB][DG];
__device__ float g_s[BB][NN];
__device__ float g_stats[BB][2];
__device__ float g_nodeagg[BB][DG];
__device__ float g_hidden[BB][1024];
// CSR-by-destination
__device__ int   g_deg[NN];
__device__ int   g_off[NN + 1];
__device__ int   g_cur[NN];
__device__ int2  g_e2[NE];

// ---------------- k0 (side stream): zero out / nodeagg / deg ----------------
__global__ __launch_bounds__(256) void k0(float* __restrict__ out) {
    int i = blockIdx.x * 256 + threadIdx.x;
    if (i < NN) g_deg[i] = 0;
    if (i < BB * NC) out[i] = 0.f;
    if (i < BB * DG) ((float*)g_nodeagg)[i] = 0.f;
}

__global__ __launch_bounds__(256) void k_hist(const int* __restrict__ edst) {
    int e = blockIdx.x * 256 + threadIdx.x;
    if (e < NE) atomicAdd(&g_deg[edst[e]], 1);
}

// hierarchical warp-shfl scan: 2 block barriers
__global__ __launch_bounds__(1024) void k_scan() {
    __shared__ int sdeg[NN];
    __shared__ int wsum[32];
    int t = threadIdx.x;
    for (int i = t; i < NN; i += 1024) sdeg[i] = g_deg[i];
    __syncthreads();
    const int CHK = 20;
    int base = t * CHK;
    int loc[CHK];
    int s = 0;
#pragma unroll
    for (int k = 0; k < CHK; k++) {
        int idx = base + k;
        int d = (idx < NN) ? sdeg[idx] : 0;
        loc[k] = s;
        s += d;
    }
    int lane = t & 31, wid = t >> 5;
    int incl = s;
#pragma unroll
    for (int off = 1; off < 32; off <<= 1) {
        int v = __shfl_up_sync(0xffffffffu, incl, off);
        if (lane >= off) incl += v;
    }
    if (lane == 31) wsum[wid] = incl;
    __syncthreads();
    if (wid == 0) {
        int v = wsum[lane];
        int iv = v;
#pragma unroll
        for (int off = 1; off < 32; off <<= 1) {
            int u = __shfl_up_sync(0xffffffffu, iv, off);
            if (lane >= off) iv += u;
        }
        wsum[lane] = iv - v;
    }
    __syncthreads();
    int texcl = wsum[wid] + incl - s;
#pragma unroll
    for (int k = 0; k < CHK; k++) {
        int idx = base + k;
        if (idx < NN) { int o = texcl + loc[k]; g_off[idx] = o; g_cur[idx] = o; }
    }
    if (t == 1023) g_off[NN] = wsum[31] + incl;
}

__global__ __launch_bounds__(256) void k_fill(
    const int* __restrict__ esrc, const int* __restrict__ edst,
    const int* __restrict__ etype, const float* __restrict__ wcomp) {
    int e = blockIdx.x * 256 + threadIdx.x;
    if (e >= NE) return;
    int d = edst[e];
    int pos = atomicAdd(&g_cur[d], 1);
    g_e2[pos] = make_int2(esrc[e], __float_as_int(wcomp[etype[e]]));
}

// ---------------- k_gx: gates GEMM, 32 blocks x 384 threads ----------------
// block = (dir, chunk of 8 bt-rows); thread owns ONE gate column -> Wx read once
__global__ __launch_bounds__(384) void k_gx(
    const int* __restrict__ questions, const float* __restrict__ emb_word,
    const float* __restrict__ Wxf, const float* __restrict__ bxf,
    const float* __restrict__ Wxb, const float* __restrict__ bxb)
{
    __shared__ float xs[8][DW];
    __shared__ int toks[8];
    int blk = blockIdx.x;
    int dir = blk >> 4, chunk = blk & 15;
    const float* Wx = dir ? Wxb : Wxf;
    const float* bx = dir ? bxb : bxf;
    int tid = threadIdx.x;
    int p0 = chunk * 8;
    if (tid < 8) toks[tid] = questions[p0 + tid];
    __syncthreads();
    for (int i = tid; i < 8 * DW; i += 384) {
        int pp = i / DW, k = i - pp * DW;
        xs[pp][k] = emb_word[(size_t)toks[pp] * DW + k];
    }
    __syncthreads();
    int g = tid;  // 0..383
    float acc[8] = {};
    for (int i = 0; i < DW; i++) {
        float wv = Wx[i * H3 + g];
#pragma unroll
        for (int pp = 0; pp < 8; pp++) acc[pp] += xs[pp][i] * wv;
    }
    float bg = bx[g];
#pragma unroll
    for (int pp = 0; pp < 8; pp++) {
        int bt = p0 + pp;
        int b = bt >> 5, t = bt & 31;
        int ts = dir ? (TT - 1 - t) : t;
        g_gx[dir][b][ts][g] = acc[pp] + bg;
    }
}

// ---------------- k_gru: scan only, Wh register-resident, gx prefetched ----------------
__global__ __launch_bounds__(768, 1) void k_gru(
    const int* __restrict__ questions,
    const float* __restrict__ Whf, const float* __restrict__ bhf,
    const float* __restrict__ Whb, const float* __restrict__ bhb)
{
    __shared__ float hs[HD];
    __shared__ float gsh[H3];
    __shared__ int msk[TT];
    int blk = blockIdx.x;
    int dir = blk >> 2, b = blk & 3;
    const float* Wh = dir ? Whb : Whf;
    const float* bh = dir ? bhb : bhf;
    int tid = threadIdx.x;
    if (tid < TT) msk[tid] = questions[b * TT + tid];
    if (tid < HD) hs[tid] = 0.f;
    int col = tid >> 1, half = tid & 1;
    float w[64];
#pragma unroll
    for (int k = 0; k < 64; k++) w[k] = Wh[(half * 64 + k) * H3 + col];
    float bias = bh[col];
    __syncthreads();
    for (int t = 0; t < TT; t++) {
        // prefetch this step's input gates (overlaps the FMA chain below)
        float r0 = 0.f, r1 = 0.f, r2 = 0.f;
        if (tid < HD) {
            const float* gxt = &g_gx[dir][b][t][0];
            r0 = gxt[tid]; r1 = gxt[HD + tid]; r2 = gxt[2 * HD + tid];
        }
        float a0 = 0.f, a1 = 0.f, a2 = 0.f, a3 = 0.f;
#pragma unroll
        for (int k = 0; k < 64; k += 4) {
            a0 += hs[half * 64 + k] * w[k];
            a1 += hs[half * 64 + k + 1] * w[k + 1];
            a2 += hs[half * 64 + k + 2] * w[k + 2];
            a3 += hs[half * 64 + k + 3] * w[k + 3];
        }
        float acc = (a0 + a1) + (a2 + a3);
        acc += __shfl_xor_sync(0xffffffffu, acc, 1);
        if (half == 0) gsh[col] = acc + bias;
        __syncthreads();
        if (tid < HD) {
            float r = 1.f / (1.f + expf(-(r0 + gsh[tid])));
            float z = 1.f / (1.f + expf(-(r1 + gsh[HD + tid])));
            float n = tanhf(r2 + r * gsh[2 * HD + tid]);
            float h = hs[tid];
            float hnew = (1.f - z) * n + z * h;
            int torig = dir ? (TT - 1 - t) : t;
            hs[tid] = (msk[torig] != 0) ? hnew : h;
        }
        __syncthreads();
    }
    if (tid < HD) g_qemb[b][dir * HD + tid] = hs[tid];
}

// ---------------- q_g = q_emb @ W_hg + b_hg (32 blocks) ----------------
__global__ __launch_bounds__(256) void k_qg(const float* __restrict__ Whg, const float* __restrict__ bhg) {
    int blk = blockIdx.x;
    int b = blk >> 3, og = blk & 7;
    int i = threadIdx.x;
    float x = g_qemb[b][i];
    const float4* W4 = (const float4*)Whg;
    float4 wA = W4[i * 16 + og * 2];
    float4 wB = W4[i * 16 + og * 2 + 1];
    float p[8] = { x * wA.x, x * wA.y, x * wA.z, x * wA.w,
                   x * wB.x, x * wB.y, x * wB.z, x * wB.w };
#pragma unroll
    for (int o = 0; o < 8; o++)
#pragma unroll
        for (int off = 16; off; off >>= 1)
            p[o] += __shfl_down_sync(0xffffffffu, p[o], off);
    __shared__ float red[8][8];
    int wid = i >> 5, lane = i & 31;
    if (lane == 0)
#pragma unroll
        for (int o = 0; o < 8; o++) red[o][wid] = p[o];
    __syncthreads();
    if (i < 8) {
        float s = bhg[og * 8 + i];
#pragma unroll
        for (int k = 0; k < 8; k++) s += red[i][k];
        g_qg[b][og * 8 + i] = s;
    }
}

// ---------------- per-token precompute (1024 threads, 32 tokens/block) ----------------
__global__ __launch_bounds__(1024) void k_tok(
    const float* __restrict__ emb_desc, const float* __restrict__ bases)
{
    __shared__ float sW0[DG * DG];
    __shared__ float sQg[BB][DG];
    __shared__ float sE[32][DG];
    int tid = threadIdx.x;
    for (int i = tid; i < DG * DG; i += 1024) sW0[i] = bases[i];
    if (tid < BB * DG) ((float*)sQg)[tid] = ((const float*)g_qg)[tid];
    __syncthreads();
    int w = tid >> 5, lane = tid & 31;
    int v = blockIdx.x * 32 + w;
    if (v >= VD) return;
    float2 e = ((const float2*)(emb_desc + (size_t)v * DG))[lane];
    sE[w][2 * lane] = e.x;
    sE[w][2 * lane + 1] = e.y;
    __syncwarp();
    float p0 = e.x * sQg[0][2 * lane] + e.y * sQg[0][2 * lane + 1];
    float p1 = e.x * sQg[1][2 * lane] + e.y * sQg[1][2 * lane + 1];
    float p2 = e.x * sQg[2][2 * lane] + e.y * sQg[2][2 * lane + 1];
    float p3 = e.x * sQg[3][2 * lane] + e.y * sQg[3][2 * lane + 1];
#pragma unroll
    for (int off = 16; off; off >>= 1) {
        p0 += __shfl_xor_sync(0xffffffffu, p0, off);
        p1 += __shfl_xor_sync(0xffffffffu, p1, off);
        p2 += __shfl_xor_sync(0xffffffffu, p2, off);
        p3 += __shfl_xor_sync(0xffffffffu, p3, off);
    }
    if (lane == 0) g_tokdot[v] = make_float4(p0, p1, p2, p3);
    float ax = 0.f, ay = 0.f;
#pragma unroll
    for (int d = 0; d < DG; d++) {
        float fv = sE[w][d];
        float2 wv = *(float2*)&sW0[d * DG + 2 * lane];
        ax += fv * wv.x;
        ay += fv * wv.y;
    }
    ((float2*)(g_P + (size_t)v * DG))[lane] = make_float2(ax, ay);
}

// ---------------- per-node softmax + weighted sum of P rows ----------------
__global__ __launch_bounds__(256) void k_node(const int* __restrict__ node_descs) {
    int tid = threadIdx.x;
    int w = tid >> 5, lane = tid & 31;
    int n = blockIdx.x * 8 + w;
    if (n >= NN) return;
    int tok = 0;
    float4 dv = make_float4(-1e30f, -1e30f, -1e30f, -1e30f);
    if (lane < DESC) {
        tok = node_descs[n * DESC + lane];
        dv = g_tokdot[tok];
    }
    float4 m = dv;
#pragma unroll
    for (int off = 8; off; off >>= 1) {
        m.x = fmaxf(m.x, __shfl_xor_sync(0xffffffffu, m.x, off, 16));
        m.y = fmaxf(m.y, __shfl_xor_sync(0xffffffffu, m.y, off, 16));
        m.z = fmaxf(m.z, __shfl_xor_sync(0xffffffffu, m.z, off, 16));
        m.w = fmaxf(m.w, __shfl_xor_sync(0xffffffffu, m.w, off, 16));
    }
    float4 ev;
    ev.x = expf(dv.x - m.x); ev.y = expf(dv.y - m.y);
    ev.z = expf(dv.z - m.z); ev.w = expf(dv.w - m.w);
    float4 s = ev;
#pragma unroll
    for (int off = 8; off; off >>= 1) {
        s.x += __shfl_xor_sync(0xffffffffu, s.x, off, 16);
        s.y += __shfl_xor_sync(0xffffffffu, s.y, off, 16);
        s.z += __shfl_xor_sync(0xffffffffu, s.z, off, 16);
        s.w += __shfl_xor_sync(0xffffffffu, s.w, off, 16);
    }
    float4 wt;
    wt.x = ev.x / s.x; wt.y = ev.y / s.y; wt.z = ev.z / s.z; wt.w = ev.w / s.w;
    float2 acc0 = make_float2(0.f, 0.f), acc1 = acc0, acc2 = acc0, acc3 = acc0;
#pragma unroll
    for (int i = 0; i < DESC; i++) {
        int ti = __shfl_sync(0xffffffffu, tok, i);
        float w0 = __shfl_sync(0xffffffffu, wt.x, i);
        float w1 = __shfl_sync(0xffffffffu, wt.y, i);
        float w2 = __shfl_sync(0xffffffffu, wt.z, i);
        float w3 = __shfl_sync(0xffffffffu, wt.w, i);
        float2 pv = ((const float2*)(g_P + (size_t)ti * DG))[lane];
        acc0.x += w0 * pv.x; acc0.y += w0 * pv.y;
        acc1.x += w1 * pv.x; acc1.y += w1 * pv.y;
        acc2.x += w2 * pv.x; acc2.y += w2 * pv.y;
        acc3.x += w3 * pv.x; acc3.y += w3 * pv.y;
    }
    ((float2*)&g_hb[n][0][0])[lane] = acc0;
    ((float2*)&g_hb[n][1][0])[lane] = acc1;
    ((float2*)&g_hb[n][2][0])[lane] = acc2;
    ((float2*)&g_hb[n][3][0])[lane] = acc3;
}

// ---------------- CSR gather: one warp per (node, batch) ----------------
__global__ __launch_bounds__(256) void k_gather(const float* __restrict__ rbias) {
    int w = threadIdx.x >> 5, lane = threadIdx.x & 31;
    int n = blockIdx.x * 2 + (w >> 2);
    int b = w & 3;
    if (n >= NN) return;
    int off = g_off[n], end = g_off[n + 1];
    float2 aA = make_float2(0.f, 0.f), aB = aA;
    const float2* hb2 = (const float2*)g_hb;
    for (int base = off; base < end; base += 32) {
        int ii = base + lane;
        int2 ed = (ii < end) ? g_e2[ii] : make_int2(0, 0);
        int m = min(32, end - base);
        int j = 0;
        for (; j + 2 <= m; j += 2) {
            int s0 = __shfl_sync(0xffffffffu, ed.x, j);
            float c0 = __int_as_float(__shfl_sync(0xffffffffu, ed.y, j));
            int s1 = __shfl_sync(0xffffffffu, ed.x, j + 1);
            float c1 = __int_as_float(__shfl_sync(0xffffffffu, ed.y, j + 1));
            float2 v0 = hb2[(s0 * 4 + b) * 32 + lane];
            float2 v1 = hb2[(s1 * 4 + b) * 32 + lane];
            aA.x += c0 * v0.x; aA.y += c0 * v0.y;
            aB.x += c1 * v1.x; aB.y += c1 * v1.y;
        }
        if (j < m) {
            int s0 = __shfl_sync(0xffffffffu, ed.x, j);
            float c0 = __int_as_float(__shfl_sync(0xffffffffu, ed.y, j));
            float2 v0 = hb2[(s0 * 4 + b) * 32 + lane];
            aA.x += c0 * v0.x; aA.y += c0 * v0.y;
        }
    }
    float2 a = make_float2(aA.x + aB.x, aA.y + aB.y);
    float2 rb = ((const float2*)rbias)[lane];
    a.x = fmaxf(a.x + rb.x, 0.f);
    a.y = fmaxf(a.y + rb.y, 0.f);
    ((float2*)g_agg)[(n * 4 + b) * 32 + lane] = a;
    float2 q = ((const float2*)g_qg)[b * 32 + lane];
    float p = a.x * q.x + a.y * q.y;
#pragma unroll
    for (int o = 16; o; o >>= 1) p += __shfl_down_sync(0xffffffffu, p, o);
    if (lane == 0) g_s[b][n] = p;
}

// ---------------- softmax stats over nodes (4 blocks) ----------------
__global__ __launch_bounds__(512) void k_stats() {
    int b = blockIdx.x, tid = threadIdx.x;
    __shared__ float red[512];
    float m = -1e30f;
    for (int n = tid; n < NN; n += 512) m = fmaxf(m, g_s[b][n]);
    red[tid] = m;
    __syncthreads();
    for (int s = 256; s; s >>= 1) {
        if (tid < s) red[tid] = fmaxf(red[tid], red[tid + s]);
        __syncthreads();
    }
    m = red[0];
    __syncthreads();
    float sum = 0.f;
    for (int n = tid; n < NN; n += 512) sum += expf(g_s[b][n] - m);
    red[tid] = sum;
    __syncthreads();
    for (int s = 256; s; s >>= 1) {
        if (tid < s) red[tid] += red[tid + s];
        __syncthreads();
    }
    if (tid == 0) { g_stats[b][0] = m; g_stats[b][1] = 1.f / red[0]; }
}

// ---------------- attention pooling ----------------
#define CH 256
__global__ __launch_bounds__(256) void k_pool() {
    const int nch = (NN + CH - 1) / CH;
    int b = blockIdx.x / nch, c = blockIdx.x % nch;
    int n0 = c * CH;
    __shared__ float p[CH];
    __shared__ float part[4][DG];
    int tid = threadIdx.x;
    float m = g_stats[b][0], inv = g_stats[b][1];
    int n = n0 + tid;
    p[tid] = (n < NN) ? expf(g_s[b][n] - m) * inv : 0.f;
    __syncthreads();
    int d = tid & 63, g = tid >> 6;
    float acc = 0.f;
    for (int nl = g; nl < CH; nl += 4) {
        int nn2 = n0 + nl;
        if (nn2 < NN) acc += p[nl] * g_agg[nn2][b][d];
    }
    part[g][d] = acc;
    __syncthreads();
    if (tid < DG)
        atomicAdd(&g_nodeagg[b][tid], part[0][tid] + part[1][tid] + part[2][tid] + part[3][tid]);
}

// ---------------- classifier ----------------
__global__ __launch_bounds__(256) void k_fc1(const float* __restrict__ W1, const float* __restrict__ b1) {
    __shared__ float feat[BB][DG + DH];
    int tid = threadIdx.x;
    for (int i = tid; i < BB * (DG + DH); i += 256) {
        int b = i / (DG + DH), k = i % (DG + DH);
        feat[b][k] = (k < DG) ? g_nodeagg[b][k] : g_qemb[b][k - DG];
    }
    __syncthreads();
    int j = blockIdx.x * 256 + tid;
    float acc[BB] = {};
    for (int i = 0; i < DG + DH; i++) {
        float w = W1[i * 1024 + j];
#pragma unroll
        for (int b = 0; b < BB; b++) acc[b] += feat[b][i] * w;
    }
    float bj = b1[j];
#pragma unroll
    for (int b = 0; b < BB; b++) g_hidden[b][j] = fmaxf(acc[b] + bj, 0.f);
}

// split-K fc2: 8 j-blocks x 8 i-chunks (128 each)
__global__ __launch_bounds__(256) void k_fc2(const float* __restrict__ W2, const float* __restrict__ b2,
                                             float* __restrict__ out) {
    int jb = blockIdx.x & 7, chunk = blockIdx.x >> 3;
    __shared__ float h[BB][128];
    int tid = threadIdx.x;
    if (tid < 128) {
#pragma unroll
        for (int b = 0; b < BB; b++) h[b][tid] = g_hidden[b][chunk * 128 + tid];
    }
    __syncthreads();
    int j = jb * 256 + tid;
    if (j >= NC) return;
    float acc[BB] = {};
    for (int i = 0; i < 128; i++) {
        float w = W2[(size_t)(chunk * 128 + i) * NC + j];
#pragma unroll
        for (int b = 0; b < BB; b++) acc[b] += h[b][i] * w;
    }
    float bj = (chunk == 0) ? b2[j] : 0.f;
#pragma unroll
    for (int b = 0; b < BB; b++) atomicAdd(&out[b * NC + j], acc[b] + bj);
}

// ---------------- launch ----------------
extern "C" void kernel_launch(void* const* d_in, const int* in_sizes, int n_in,
                              void* d_out, int out_size) {
    const int*   questions  = (const int*)d_in[0];
    const int*   node_descs = (const int*)d_in[1];
    const int*   edge_src   = (const int*)d_in[2];
    const int*   edge_dst   = (const int*)d_in[3];
    const int*   edge_type  = (const int*)d_in[4];
    const float* emb_word   = (const float*)d_in[5];
    const float* emb_desc   = (const float*)d_in[6];
    const float* Wx_f       = (const float*)d_in[7];
    const float* Wh_f       = (const float*)d_in[8];
    const float* bx_f       = (const float*)d_in[9];
    const float* bh_f       = (const float*)d_in[10];
    const float* Wx_b       = (const float*)d_in[11];
    const float* Wh_b       = (const float*)d_in[12];
    const float* bx_b       = (const float*)d_in[13];
    const float* bh_b       = (const float*)d_in[14];
    const float* W_hg       = (const float*)d_in[15];
    const float* b_hg       = (const float*)d_in[16];
    const float* bases      = (const float*)d_in[17];
    const float* w_comp     = (const float*)d_in[18];
    const float* rgcn_bias  = (const float*)d_in[19];
    const float* W1         = (const float*)d_in[20];
    const float* b1         = (const float*)d_in[21];
    const float* W2         = (const float*)d_in[22];
    const float* b2         = (const float*)d_in[23];
    float* out = (float*)d_out;

    static cudaStream_t s2 = 0;
    static cudaEvent_t evFork = 0, evCSR = 0;
    static int inited = 0;
    if (!inited) {
        cudaStreamCreateWithFlags(&s2, cudaStreamNonBlocking);
        cudaEventCreateWithFlags(&evFork, cudaEventDisableTiming);
        cudaEventCreateWithFlags(&evCSR, cudaEventDisableTiming);
        inited = 1;
    }

    // fork side stream immediately: k0 + CSR build run entirely off the main chain
    cudaEventRecord(evFork, 0);
    cudaStreamWaitEvent(s2, evFork, 0);
    k0<<<(NN + 255) / 256, 256, 0, s2>>>(out);
    k_hist<<<(NE + 255) / 256, 256, 0, s2>>>(edge_dst);
    k_scan<<<1, 1024, 0, s2>>>();
    k_fill<<<(NE + 255) / 256, 256, 0, s2>>>(edge_src, edge_dst, edge_type, w_comp);
    cudaEventRecord(evCSR, s2);

    // main chain: question encoding + node features
    k_gx<<<32, 384>>>(questions, emb_word, Wx_f, bx_f, Wx_b, bx_b);
    k_gru<<<8, 768>>>(questions, Wh_f, bh_f, Wh_b, bh_b);
    k_qg<<<32, 256>>>(W_hg, b_hg);
    k_tok<<<(VD + 31) / 32, 1024>>>(emb_desc, bases);
    k_node<<<(NN + 7) / 8, 256>>>(node_descs);

    // join CSR, then gather + rest
    cudaStreamWaitEvent(0, evCSR, 0);
    k_gather<<<(NN + 1) / 2, 256>>>(rgcn_bias);
    k_stats<<<4, 512>>>();
    k_pool<<<4 * ((NN + CH - 1) / CH), 256>>>();
    k_fc1<<<4, 256>>>(W1, b1);
    k_fc2<<<64, 256>>>(W2, b2, out);
}